// round 4
// baseline (speedup 1.0000x reference)
#include <cuda_runtime.h>
#include <cuda_bf16.h>

#define SEQ    2048
#define NBATCH 4
#define DMODEL 768
#define NHEAD  12
#define DHEAD  64
#define MROWS  (NBATCH * SEQ)   // 8192

typedef __nv_bfloat16 bf16;
typedef __nv_bfloat162 bf162;

// ---------------- device scratch ----------------
__device__ bf16 g_xh[MROWS * DMODEL];
__device__ bf16 g_xl[MROWS * DMODEL];
__device__ bf16 g_wqh[3 * DMODEL * DMODEL];   // transposed [N][K]
__device__ bf16 g_wql[3 * DMODEL * DMODEL];
__device__ bf16 g_woh[DMODEL * DMODEL];       // transposed [N][K]
__device__ bf16 g_wol[DMODEL * DMODEL];
__device__ bf16 g_qh[NBATCH * NHEAD * SEQ * DHEAD];
__device__ bf16 g_ql[NBATCH * NHEAD * SEQ * DHEAD];
__device__ bf16 g_kh[NBATCH * NHEAD * SEQ * DHEAD];
__device__ bf16 g_kl[NBATCH * NHEAD * SEQ * DHEAD];
__device__ bf16 g_vh[NBATCH * NHEAD * SEQ * DHEAD];
__device__ bf16 g_vl[NBATCH * NHEAD * SEQ * DHEAD];
__device__ bf16 g_ch[MROWS * DMODEL];
__device__ bf16 g_cl[MROWS * DMODEL];

// ---------------- helpers ----------------
__device__ __forceinline__ unsigned smem_u32(const void* p) {
    unsigned a;
    asm("{ .reg .u64 t; cvta.to.shared.u64 t, %1; cvt.u32.u64 %0, t; }"
        : "=r"(a) : "l"(p));
    return a;
}
__device__ __forceinline__ void ldsm_x4(unsigned r[4], unsigned addr) {
    asm volatile("ldmatrix.sync.aligned.m8n8.x4.shared.b16 {%0,%1,%2,%3}, [%4];"
                 : "=r"(r[0]), "=r"(r[1]), "=r"(r[2]), "=r"(r[3]) : "r"(addr));
}
__device__ __forceinline__ void ldsm_x4_t(unsigned r[4], unsigned addr) {
    asm volatile("ldmatrix.sync.aligned.m8n8.x4.trans.shared.b16 {%0,%1,%2,%3}, [%4];"
                 : "=r"(r[0]), "=r"(r[1]), "=r"(r[2]), "=r"(r[3]) : "r"(addr));
}
__device__ __forceinline__ void mma16816(float c[4], const unsigned a[4],
                                         unsigned b0, unsigned b1) {
    asm volatile(
        "mma.sync.aligned.m16n8k16.row.col.f32.bf16.bf16.f32 "
        "{%0,%1,%2,%3}, {%4,%5,%6,%7}, {%8,%9}, {%0,%1,%2,%3};"
        : "+f"(c[0]), "+f"(c[1]), "+f"(c[2]), "+f"(c[3])
        : "r"(a[0]), "r"(a[1]), "r"(a[2]), "r"(a[3]), "r"(b0), "r"(b1));
}
__device__ __forceinline__ void cpa16(unsigned saddr, const void* g) {
    asm volatile("cp.async.cg.shared.global [%0], [%1], 16;"
                 :: "r"(saddr), "l"(g));
}
#define CP_COMMIT() asm volatile("cp.async.commit_group;" ::: "memory")
#define CP_WAIT(N)  asm volatile("cp.async.wait_group %0;" :: "n"(N) : "memory")

__device__ __forceinline__ unsigned pack_hi(float a, float b) {
    bf162 t;
    t.x = __float2bfloat16(a);
    t.y = __float2bfloat16(b);
    return *(unsigned*)&t;
}
__device__ __forceinline__ unsigned pack_lo(float a, float b, unsigned hi) {
    bf162 h = *(bf162*)&hi;
    bf162 t;
    t.x = __float2bfloat16(a - __bfloat162float(h.x));
    t.y = __float2bfloat16(b - __bfloat162float(h.y));
    return *(unsigned*)&t;
}

// ---------------------------------------------------------------------------
// HMMA GEMM: C[M,N] = A[M,K] * B[N,K]^T, bf16x3, cp.async double-buffered.
// CTA 128x128, BK=64, 256 thr, 8 warps each 64x32.
// ---------------------------------------------------------------------------
#define GLD 72
#define GSTAGE (4 * 128 * GLD)            // elements per stage
#define GEMM_SMEM (2 * GSTAGE * 2)        // bytes

template <int MODE, int ND>
__global__ __launch_bounds__(256, 1)
void mma_gemm(const bf16* __restrict__ Ah, const bf16* __restrict__ Al,
              const bf16* __restrict__ Bh, const bf16* __restrict__ Bl,
              float* __restrict__ C)
{
    constexpr int KD = DMODEL;            // 768, 12 chunks of 64
    constexpr int NCH = KD / 64;
    extern __shared__ bf16 sm[];

    const int tid = threadIdx.x, wid = tid >> 5, lane = tid & 31;
    const int m0 = blockIdx.y * 128, n0 = blockIdx.x * 128;
    const int rowbase = (wid & 1) * 64;
    const int colbase = (wid >> 1) * 32;

    // prefetch issue: 4 reps x 4 arrays of 16B per thread
    auto issue = [&](int k0, int buf) {
        bf16* st = sm + buf * GSTAGE;
        const unsigned sb = smem_u32(st);
#pragma unroll
        for (int rep = 0; rep < 4; rep++) {
            const int idx = tid + rep * 256;
            const int row = idx >> 3, ch = (idx & 7) * 8;
            const unsigned so = (row * GLD + ch) * 2;
            const size_t ga = (size_t)(m0 + row) * KD + k0 + ch;
            const size_t gb = (size_t)(n0 + row) * KD + k0 + ch;
            cpa16(sb + so,                      &Ah[ga]);
            cpa16(sb + 128 * GLD * 2 + so,      &Al[ga]);
            cpa16(sb + 2 * 128 * GLD * 2 + so,  &Bh[gb]);
            cpa16(sb + 3 * 128 * GLD * 2 + so,  &Bl[gb]);
        }
        CP_COMMIT();
    };

    float acc[4][4][4];
#pragma unroll
    for (int a = 0; a < 4; a++)
#pragma unroll
        for (int b = 0; b < 4; b++)
#pragma unroll
            for (int c = 0; c < 4; c++) acc[a][b][c] = 0.0f;

    issue(0, 0);
    for (int ch = 0; ch < NCH; ch++) {
        const int buf = ch & 1;
        if (ch + 1 < NCH) { issue((ch + 1) * 64, buf ^ 1); CP_WAIT(1); }
        else              { CP_WAIT(0); }
        __syncthreads();

        bf16* sAh = sm + buf * GSTAGE;
        bf16* sAl = sAh + 128 * GLD;
        bf16* sBh = sAl + 128 * GLD;
        bf16* sBl = sBh + 128 * GLD;

#pragma unroll
        for (int ks = 0; ks < 4; ks++) {
            const int fc = ks * 16 + (lane >> 4) * 8;
            unsigned ah[4][4], al[4][4];
#pragma unroll
            for (int mi = 0; mi < 4; mi++) {
                const int r = rowbase + mi * 16 + (lane & 15);
                ldsm_x4(ah[mi], smem_u32(&sAh[r * GLD + fc]));
                ldsm_x4(al[mi], smem_u32(&sAl[r * GLD + fc]));
            }
            unsigned bh[2][4], bl[2][4];
#pragma unroll
            for (int g = 0; g < 2; g++) {
                const int r = colbase + g * 16 + (lane & 15);
                ldsm_x4(bh[g], smem_u32(&sBh[r * GLD + fc]));
                ldsm_x4(bl[g], smem_u32(&sBl[r * GLD + fc]));
            }
#pragma unroll
            for (int mi = 0; mi < 4; mi++)
#pragma unroll
                for (int nj = 0; nj < 4; nj++) {
                    const int g = nj >> 1, o = nj & 1;
                    mma16816(acc[mi][nj], ah[mi], bh[g][o], bh[g][o + 2]);
                    mma16816(acc[mi][nj], ah[mi], bl[g][o], bl[g][o + 2]);
                    mma16816(acc[mi][nj], al[mi], bh[g][o], bh[g][o + 2]);
                }
        }
        __syncthreads();   // all reads of buf done before it is refilled
    }

    const int r0 = lane >> 2, c0 = (lane & 3) * 2;
    if (MODE == 0) {
#pragma unroll
        for (int mi = 0; mi < 4; mi++)
#pragma unroll
            for (int nj = 0; nj < 4; nj++) {
                const int row = m0 + rowbase + mi * 16 + r0;
                const int col = n0 + colbase + nj * 8 + c0;
                float2 v0 = make_float2(acc[mi][nj][0], acc[mi][nj][1]);
                float2 v1 = make_float2(acc[mi][nj][2], acc[mi][nj][3]);
                *(float2*)&C[(size_t)row * ND + col] = v0;
                *(float2*)&C[(size_t)(row + 8) * ND + col] = v1;
            }
    } else {
#pragma unroll
        for (int nj = 0; nj < 4; nj++) {
            const int jg    = n0 + colbase + nj * 8;
            const int which = jg / DMODEL;
            const int rem   = jg - which * DMODEL;
            const int h     = rem >> 6;
            const int dh    = (rem & 63) + c0;
            bf16* dsth = (which == 0) ? g_qh : (which == 1) ? g_kh : g_vh;
            bf16* dstl = (which == 0) ? g_ql : (which == 1) ? g_kl : g_vl;
#pragma unroll
            for (int mi = 0; mi < 4; mi++) {
                const int m  = m0 + rowbase + mi * 16 + r0;
                const int b_ = m >> 11;
                const int n_ = m & (SEQ - 1);
                const size_t d0 =
                    ((size_t)(b_ * NHEAD + h) * SEQ + n_) * DHEAD + dh;
                unsigned h0 = pack_hi(acc[mi][nj][0], acc[mi][nj][1]);
                unsigned l0 = pack_lo(acc[mi][nj][0], acc[mi][nj][1], h0);
                *(unsigned*)&dsth[d0] = h0;
                *(unsigned*)&dstl[d0] = l0;
                const size_t d1 = d0 + 8 * DHEAD;
                unsigned h1 = pack_hi(acc[mi][nj][2], acc[mi][nj][3]);
                unsigned l1 = pack_lo(acc[mi][nj][2], acc[mi][nj][3], h1);
                *(unsigned*)&dsth[d1] = h1;
                *(unsigned*)&dstl[d1] = l1;
            }
        }
    }
}

// ---------------------------------------------------------------------------
// HMMA flash attention, causal. BM=128 (8 warps, m16/warp), BN=64.
// cp.async double-buffered K/V; bf16x3 QK^T and PV; warp-level tile skipping.
// ---------------------------------------------------------------------------
#define ALD 72
#define AQ_ELE (128 * ALD)                 // per Q array
#define ASTAGE (4 * 64 * ALD)              // Kh,Kl,Vh,Vl per stage
#define ATTN_SMEM ((2 * AQ_ELE + 2 * ASTAGE) * 2)

__global__ __launch_bounds__(256, 1)
void attn_mma()
{
    extern __shared__ bf16 asm_[];
    bf16* sQh = asm_;
    bf16* sQl = sQh + AQ_ELE;
    bf16* stg = sQl + AQ_ELE;              // 2 stages

    const int tid = threadIdx.x, wid = tid >> 5, lane = tid & 31;
    const int qt = blockIdx.x, bh = blockIdx.y;
    const int q0 = qt * 128;
    const int mo = wid * 16;
    const int r0 = lane >> 2, c0 = (lane & 3) * 2;

    const size_t hb = (size_t)bh * SEQ * DHEAD;
    const int nt = 2 * qt + 2;             // k-tiles of 64 covering q0..q0+127

    // issue K/V tile t into stage buf
    auto issue = [&](int t, int buf) {
        bf16* st = stg + buf * ASTAGE;
        const unsigned sb = smem_u32(st);
        const int k0t = t * 64;
#pragma unroll
        for (int rep = 0; rep < 2; rep++) {
            const int idx = tid + rep * 256;
            const int row = idx >> 3, ch = (idx & 7) * 8;
            const unsigned so = (row * ALD + ch) * 2;
            const size_t g = hb + (size_t)(k0t + row) * DHEAD + ch;
            cpa16(sb + so,                     &g_kh[g]);
            cpa16(sb + 64 * ALD * 2 + so,      &g_kl[g]);
            cpa16(sb + 2 * 64 * ALD * 2 + so,  &g_vh[g]);
            cpa16(sb + 3 * 64 * ALD * 2 + so,  &g_vl[g]);
        }
        CP_COMMIT();
    };

    // load Q tile (128 rows) hi/lo
#pragma unroll
    for (int rep = 0; rep < 4; rep++) {
        const int idx = tid + rep * 256;
        const int row = idx >> 3, ch = (idx & 7) * 8;
        const size_t g = hb + (size_t)(q0 + row) * DHEAD + ch;
        *(uint4*)&sQh[row * ALD + ch] = *(const uint4*)&g_qh[g];
        *(uint4*)&sQl[row * ALD + ch] = *(const uint4*)&g_ql[g];
    }
    issue(0, 0);
    __syncthreads();

    // Q fragments (persist)
    unsigned aqh[4][4], aql[4][4];
#pragma unroll
    for (int ks = 0; ks < 4; ks++) {
        const int r = mo + (lane & 15);
        const int c = ks * 16 + (lane >> 4) * 8;
        ldsm_x4(aqh[ks], smem_u32(&sQh[r * ALD + c]));
        ldsm_x4(aql[ks], smem_u32(&sQl[r * ALD + c]));
    }

    float m_[2] = {-1e30f, -1e30f}, l_[2] = {0.0f, 0.0f};
    float o[8][4];
#pragma unroll
    for (int j = 0; j < 8; j++)
#pragma unroll
        for (int i = 0; i < 4; i++) o[j][i] = 0.0f;

    for (int t = 0; t < nt; t++) {
        const int k0t = t * 64;
        const int buf = t & 1;
        if (t + 1 < nt) { issue(t + 1, buf ^ 1); CP_WAIT(1); }
        else            { CP_WAIT(0); }
        __syncthreads();

        // this warp's rows: q0+mo .. q0+mo+15
        const bool skip = (k0t > q0 + mo + 15);
        if (!skip) {
            bf16* sKh = stg + buf * ASTAGE;
            bf16* sKl = sKh + 64 * ALD;
            bf16* sVh = sKl + 64 * ALD;
            bf16* sVl = sVh + 64 * ALD;

            float s[8][4];
#pragma unroll
            for (int j = 0; j < 8; j++)
#pragma unroll
                for (int i = 0; i < 4; i++) s[j][i] = 0.0f;

#pragma unroll
            for (int ks = 0; ks < 4; ks++) {
                const int fc = ks * 16 + (lane >> 4) * 8;
                unsigned kh[4][4], kl[4][4];
#pragma unroll
                for (int g = 0; g < 4; g++) {
                    const int r = g * 16 + (lane & 15);
                    ldsm_x4(kh[g], smem_u32(&sKh[r * ALD + fc]));
                    ldsm_x4(kl[g], smem_u32(&sKl[r * ALD + fc]));
                }
#pragma unroll
                for (int nj = 0; nj < 8; nj++) {
                    const int g = nj >> 1, oo = nj & 1;
                    mma16816(s[nj], aqh[ks], kh[g][oo], kh[g][oo + 2]);
                    mma16816(s[nj], aqh[ks], kl[g][oo], kl[g][oo + 2]);
                    mma16816(s[nj], aql[ks], kh[g][oo], kh[g][oo + 2]);
                }
            }
#pragma unroll
            for (int j = 0; j < 8; j++)
#pragma unroll
                for (int i = 0; i < 4; i++) s[j][i] *= 0.125f;

            if (k0t + 63 > q0 + mo) {      // boundary tile for this warp
                const int rA = q0 + mo + r0, rB = rA + 8;
#pragma unroll
                for (int nj = 0; nj < 8; nj++) {
                    const int cb = k0t + nj * 8 + c0;
                    if (cb > rA)     s[nj][0] = -1e30f;
                    if (cb + 1 > rA) s[nj][1] = -1e30f;
                    if (cb > rB)     s[nj][2] = -1e30f;
                    if (cb + 1 > rB) s[nj][3] = -1e30f;
                }
            }

            // online softmax
#pragma unroll
            for (int h = 0; h < 2; h++) {
                float mx = -1e30f;
#pragma unroll
                for (int nj = 0; nj < 8; nj++)
                    mx = fmaxf(mx, fmaxf(s[nj][2 * h], s[nj][2 * h + 1]));
                mx = fmaxf(mx, __shfl_xor_sync(0xffffffffu, mx, 1));
                mx = fmaxf(mx, __shfl_xor_sync(0xffffffffu, mx, 2));
                const float mnew = fmaxf(m_[h], mx);
                const float corr = __expf(m_[h] - mnew);
                float rs = 0.0f;
#pragma unroll
                for (int nj = 0; nj < 8; nj++) {
                    const float p0 = __expf(s[nj][2 * h] - mnew);
                    const float p1 = __expf(s[nj][2 * h + 1] - mnew);
                    s[nj][2 * h] = p0;
                    s[nj][2 * h + 1] = p1;
                    rs += p0 + p1;
                }
                rs += __shfl_xor_sync(0xffffffffu, rs, 1);
                rs += __shfl_xor_sync(0xffffffffu, rs, 2);
                l_[h] = l_[h] * corr + rs;
                m_[h] = mnew;
#pragma unroll
                for (int nj = 0; nj < 8; nj++) {
                    o[nj][2 * h] *= corr;
                    o[nj][2 * h + 1] *= corr;
                }
            }

            // P -> A fragments hi/lo (register reuse)
            unsigned pah[4][4], pal[4][4];
#pragma unroll
            for (int ks = 0; ks < 4; ks++) {
                pah[ks][0] = pack_hi(s[2 * ks][0], s[2 * ks][1]);
                pal[ks][0] = pack_lo(s[2 * ks][0], s[2 * ks][1], pah[ks][0]);
                pah[ks][1] = pack_hi(s[2 * ks][2], s[2 * ks][3]);
                pal[ks][1] = pack_lo(s[2 * ks][2], s[2 * ks][3], pah[ks][1]);
                pah[ks][2] = pack_hi(s[2 * ks + 1][0], s[2 * ks + 1][1]);
                pal[ks][2] = pack_lo(s[2 * ks + 1][0], s[2 * ks + 1][1], pah[ks][2]);
                pah[ks][3] = pack_hi(s[2 * ks + 1][2], s[2 * ks + 1][3]);
                pal[ks][3] = pack_lo(s[2 * ks + 1][2], s[2 * ks + 1][3], pah[ks][3]);
            }

            // O += P V  (V via ldmatrix.trans)
#pragma unroll
            for (int ks = 0; ks < 4; ks++) {
                const int rr = 16 * ks + (lane & 7) + ((lane & 16) >> 1);
                const int ccb = ((lane >> 3) & 1) * 8;
                unsigned vh[4][4], vl[4][4];
#pragma unroll
                for (int g = 0; g < 4; g++) {
                    ldsm_x4_t(vh[g], smem_u32(&sVh[rr * ALD + g * 16 + ccb]));
                    ldsm_x4_t(vl[g], smem_u32(&sVl[rr * ALD + g * 16 + ccb]));
                }
#pragma unroll
                for (int nj = 0; nj < 8; nj++) {
                    const int g = nj >> 1, oo = nj & 1;
                    mma16816(o[nj], pah[ks], vh[g][oo], vh[g][oo + 2]);
                    mma16816(o[nj], pah[ks], vl[g][oo], vl[g][oo + 2]);
                    mma16816(o[nj], pal[ks], vh[g][oo], vh[g][oo + 2]);
                }
            }
        }
        __syncthreads();   // protect stage buf before refill next iteration
    }

    // normalize + write context hi/lo in [b, n, D] layout
    const int b_ = bh / NHEAD;
    const int h_ = bh - b_ * NHEAD;
    const float inv0 = 1.0f / l_[0];
    const float inv1 = 1.0f / l_[1];
    const size_t rbase =
        ((size_t)(b_ * SEQ + q0 + mo + r0)) * DMODEL + h_ * DHEAD;
#pragma unroll
    for (int nj = 0; nj < 8; nj++) {
        const int col = nj * 8 + c0;
        const float v0 = o[nj][0] * inv0, v1 = o[nj][1] * inv0;
        unsigned h0 = pack_hi(v0, v1);
        unsigned l0 = pack_lo(v0, v1, h0);
        *(unsigned*)&g_ch[rbase + col] = h0;
        *(unsigned*)&g_cl[rbase + col] = l0;
        const float v2 = o[nj][2] * inv1, v3 = o[nj][3] * inv1;
        unsigned h1 = pack_hi(v2, v3);
        unsigned l1 = pack_lo(v2, v3, h1);
        *(unsigned*)&g_ch[rbase + 8 * DMODEL + col] = h1;
        *(unsigned*)&g_cl[rbase + 8 * DMODEL + col] = l1;
    }
}

// ---------------- conversion kernels ----------------
__global__ void cvt_pair(const float* __restrict__ src, bf16* __restrict__ hi,
                         bf16* __restrict__ lo, int n)
{
    int i = blockIdx.x * blockDim.x + threadIdx.x;
    if (i < n) {
        float x = src[i];
        bf16 h = __float2bfloat16(x);
        hi[i] = h;
        lo[i] = __float2bfloat16(x - __bfloat162float(h));
    }
}
__global__ void cvt_tr(const float* __restrict__ src, bf16* __restrict__ hi,
                       bf16* __restrict__ lo, int K, int N)
{
    int i = blockIdx.x * blockDim.x + threadIdx.x;
    if (i < K * N) {
        int k = i / N, n = i - k * N;
        float x = src[i];
        bf16 h = __float2bfloat16(x);
        hi[(size_t)n * K + k] = h;
        lo[(size_t)n * K + k] = __float2bfloat16(x - __bfloat162float(h));
    }
}

// ---------------------------------------------------------------------------
extern "C" void kernel_launch(void* const* d_in, const int* in_sizes, int n_in,
                              void* d_out, int out_size)
{
    const float* x     = (const float*)d_in[0];
    const float* w_qkv = (const float*)d_in[2];
    const float* w_out = (const float*)d_in[3];
    float* out = (float*)d_out;

    void *p_xh, *p_xl, *p_wqh, *p_wql, *p_woh, *p_wol, *p_ch, *p_cl;
    cudaGetSymbolAddress(&p_xh, g_xh);   cudaGetSymbolAddress(&p_xl, g_xl);
    cudaGetSymbolAddress(&p_wqh, g_wqh); cudaGetSymbolAddress(&p_wql, g_wql);
    cudaGetSymbolAddress(&p_woh, g_woh); cudaGetSymbolAddress(&p_wol, g_wol);
    cudaGetSymbolAddress(&p_ch, g_ch);   cudaGetSymbolAddress(&p_cl, g_cl);

    cudaFuncSetAttribute(mma_gemm<1, 3 * DMODEL>,
                         cudaFuncAttributeMaxDynamicSharedMemorySize, GEMM_SMEM);
    cudaFuncSetAttribute(mma_gemm<0, DMODEL>,
                         cudaFuncAttributeMaxDynamicSharedMemorySize, GEMM_SMEM);
    cudaFuncSetAttribute(attn_mma,
                         cudaFuncAttributeMaxDynamicSharedMemorySize, ATTN_SMEM);

    const int nx = MROWS * DMODEL;
    cvt_pair<<<(nx + 255) / 256, 256>>>(x, (bf16*)p_xh, (bf16*)p_xl, nx);
    const int nwq = DMODEL * 3 * DMODEL;
    cvt_tr<<<(nwq + 255) / 256, 256>>>(w_qkv, (bf16*)p_wqh, (bf16*)p_wql,
                                       DMODEL, 3 * DMODEL);
    const int nwo = DMODEL * DMODEL;
    cvt_tr<<<(nwo + 255) / 256, 256>>>(w_out, (bf16*)p_woh, (bf16*)p_wol,
                                       DMODEL, DMODEL);

    // 1) QKV projection -> hi/lo bf16 Q/K/V (head-major)
    mma_gemm<1, 3 * DMODEL><<<dim3(18, 64), 256, GEMM_SMEM>>>(
        (const bf16*)p_xh, (const bf16*)p_xl,
        (const bf16*)p_wqh, (const bf16*)p_wql, nullptr);

    // 2) causal flash attention (HMMA, BM=128) -> hi/lo bf16 context
    attn_mma<<<dim3(SEQ / 128, NBATCH * NHEAD), 256, ATTN_SMEM>>>();

    // 3) output projection -> d_out (fp32)
    mma_gemm<0, DMODEL><<<dim3(6, 64), 256, GEMM_SMEM>>>(
        (const bf16*)p_ch, (const bf16*)p_cl,
        (const bf16*)p_woh, (const bf16*)p_wol, out);
}